// round 1
// baseline (speedup 1.0000x reference)
#include <cuda_runtime.h>
#include <cuda_bf16.h>
#include <cstdint>
#include <cstddef>

#define E_TOT 150000
#define TE    128      // edge-rows per CTA tile
#define NT    256      // threads per CTA (8 warps)
#define SA    136      // bf16 smem row stride (128 + 8 pad)
#define SH    132      // fp32 smem row stride (128 + 4 pad), 528B = 16B-aligned rows

struct SmemT {
    __nv_bfloat16 a_hi[TE * SA];
    __nv_bfloat16 a_lo[TE * SA];
    __nv_bfloat16 w_hi[128 * SA];
    __nv_bfloat16 w_lo[128 * SA];
    float         hs[TE * SH];
};

// ---------------------------------------------------------------------------
// bf16 split helpers: v = hi + lo, each bf16; residual ~2^-17 * |v|
// ---------------------------------------------------------------------------
__device__ __forceinline__ void split2(float v, __nv_bfloat16& hi, __nv_bfloat16& lo) {
    __nv_bfloat16 h = __float2bfloat16(v);
    hi = h;
    lo = __float2bfloat16(v - __bfloat162float(h));
}

// mma.sync m16n8k16 bf16, fp32 accumulate (D += A*B)
__device__ __forceinline__ void mma16816(float d[4], const uint32_t a[4],
                                         uint32_t b0, uint32_t b1) {
    asm volatile(
        "mma.sync.aligned.m16n8k16.row.col.f32.bf16.bf16.f32 "
        "{%0,%1,%2,%3}, {%4,%5,%6,%7}, {%8,%9}, {%0,%1,%2,%3};\n"
        : "+f"(d[0]), "+f"(d[1]), "+f"(d[2]), "+f"(d[3])
        : "r"(a[0]), "r"(a[1]), "r"(a[2]), "r"(a[3]), "r"(b0), "r"(b1));
}

// Load a 128x128 fp32 weight matrix (row-major, [out][in]) -> split bf16 smem
__device__ __forceinline__ void load_w_tile(SmemT* s, const float* __restrict__ W, int tid) {
    for (int i = tid; i < (128 * 128) / 4; i += NT) {
        int r = i >> 5;
        int c = (i & 31) << 2;
        float4 v = __ldg((const float4*)(W + (size_t)r * 128 + c));
        split2(v.x, s->w_hi[r * SA + c + 0], s->w_lo[r * SA + c + 0]);
        split2(v.y, s->w_hi[r * SA + c + 1], s->w_lo[r * SA + c + 1]);
        split2(v.z, s->w_hi[r * SA + c + 2], s->w_lo[r * SA + c + 2]);
        split2(v.w, s->w_hi[r * SA + c + 3], s->w_lo[r * SA + c + 3]);
    }
}

// ---------------------------------------------------------------------------
// 128x128x128 GEMM: acc = a @ w^T using split-bf16 3-product scheme.
// Warp w: m-block = (w>>1)*32, n-block = (w&1)*64. 2x8 m16n8 tiles per warp.
// ---------------------------------------------------------------------------
__device__ __forceinline__ void gemm128(SmemT* s, float acc[2][8][4], int warp, int lane) {
#pragma unroll
    for (int mi = 0; mi < 2; mi++)
#pragma unroll
        for (int ni = 0; ni < 8; ni++)
#pragma unroll
            for (int j = 0; j < 4; j++) acc[mi][ni][j] = 0.f;

    const int mblk = (warp >> 1) << 5;
    const int nblk = (warp & 1) << 6;
    const int grp  = lane >> 2;     // 0..7
    const int tig  = lane & 3;      // 0..3

#pragma unroll 1
    for (int ks = 0; ks < 8; ks++) {
        const int k0 = ks << 4;
        uint32_t ah[2][4], al[2][4];
#pragma unroll
        for (int mi = 0; mi < 2; mi++) {
            const int r = mblk + (mi << 4) + grp;
            ah[mi][0] = *(const uint32_t*)(s->a_hi + (r    ) * SA + k0 +     (tig << 1));
            ah[mi][1] = *(const uint32_t*)(s->a_hi + (r + 8) * SA + k0 +     (tig << 1));
            ah[mi][2] = *(const uint32_t*)(s->a_hi + (r    ) * SA + k0 + 8 + (tig << 1));
            ah[mi][3] = *(const uint32_t*)(s->a_hi + (r + 8) * SA + k0 + 8 + (tig << 1));
            al[mi][0] = *(const uint32_t*)(s->a_lo + (r    ) * SA + k0 +     (tig << 1));
            al[mi][1] = *(const uint32_t*)(s->a_lo + (r + 8) * SA + k0 +     (tig << 1));
            al[mi][2] = *(const uint32_t*)(s->a_lo + (r    ) * SA + k0 + 8 + (tig << 1));
            al[mi][3] = *(const uint32_t*)(s->a_lo + (r + 8) * SA + k0 + 8 + (tig << 1));
        }
#pragma unroll
        for (int ni = 0; ni < 8; ni++) {
            const int c = nblk + (ni << 3) + grp;
            uint32_t bh0 = *(const uint32_t*)(s->w_hi + c * SA + k0 +     (tig << 1));
            uint32_t bh1 = *(const uint32_t*)(s->w_hi + c * SA + k0 + 8 + (tig << 1));
            uint32_t bl0 = *(const uint32_t*)(s->w_lo + c * SA + k0 +     (tig << 1));
            uint32_t bl1 = *(const uint32_t*)(s->w_lo + c * SA + k0 + 8 + (tig << 1));
#pragma unroll
            for (int mi = 0; mi < 2; mi++) {
                mma16816(acc[mi][ni], ah[mi], bh0, bh1);
                mma16816(acc[mi][ni], ah[mi], bl0, bl1);
                mma16816(acc[mi][ni], al[mi], bh0, bh1);
            }
        }
    }
}

// Write accumulators + bias into fp32 smem buffer hs
__device__ __forceinline__ void store_hs(SmemT* s, float acc[2][8][4],
                                         const float* __restrict__ bias, int warp, int lane) {
    const int mblk = (warp >> 1) << 5;
    const int nblk = (warp & 1) << 6;
    const int grp  = lane >> 2;
    const int tig  = lane & 3;
#pragma unroll
    for (int ni = 0; ni < 8; ni++) {
        const int c = nblk + (ni << 3) + (tig << 1);
        const float b0 = __ldg(bias + c);
        const float b1 = __ldg(bias + c + 1);
#pragma unroll
        for (int mi = 0; mi < 2; mi++) {
            const int r = mblk + (mi << 4) + grp;
            *(float2*)(s->hs + (r    ) * SH + c) = make_float2(acc[mi][ni][0] + b0, acc[mi][ni][1] + b1);
            *(float2*)(s->hs + (r + 8) * SH + c) = make_float2(acc[mi][ni][2] + b0, acc[mi][ni][3] + b1);
        }
    }
}

// Row-wise LayerNorm + SiLU over hs, writing split-bf16 result to a_hi/a_lo.
// Each warp owns 16 rows; each lane owns 4 columns.
__device__ __forceinline__ void ln_silu(SmemT* s, const float* __restrict__ lw,
                                        const float* __restrict__ lb, int warp, int lane) {
    const float4 wv = __ldg((const float4*)(lw + lane * 4));
    const float4 bv = __ldg((const float4*)(lb + lane * 4));
    for (int rr = 0; rr < 16; rr++) {
        const int r = (warp << 4) + rr;
        float4 v = *(const float4*)(s->hs + r * SH + lane * 4);
        float sum = v.x + v.y + v.z + v.w;
        float sq  = v.x * v.x + v.y * v.y + v.z * v.z + v.w * v.w;
#pragma unroll
        for (int off = 16; off > 0; off >>= 1) {
            sum += __shfl_xor_sync(0xFFFFFFFFu, sum, off);
            sq  += __shfl_xor_sync(0xFFFFFFFFu, sq,  off);
        }
        const float m   = sum * (1.0f / 128.0f);
        const float var = fmaf(-m, m, sq * (1.0f / 128.0f));
        const float inv = rsqrtf(var + 1e-5f);

        float y0 = (v.x - m) * inv * wv.x + bv.x;
        float y1 = (v.y - m) * inv * wv.y + bv.y;
        float y2 = (v.z - m) * inv * wv.z + bv.z;
        float y3 = (v.w - m) * inv * wv.w + bv.w;
        y0 = y0 / (1.0f + __expf(-y0));
        y1 = y1 / (1.0f + __expf(-y1));
        y2 = y2 / (1.0f + __expf(-y2));
        y3 = y3 / (1.0f + __expf(-y3));

        const int idx = r * SA + lane * 4;
        split2(y0, s->a_hi[idx + 0], s->a_lo[idx + 0]);
        split2(y1, s->a_hi[idx + 1], s->a_lo[idx + 1]);
        split2(y2, s->a_hi[idx + 2], s->a_lo[idx + 2]);
        split2(y3, s->a_hi[idx + 3], s->a_lo[idx + 3]);
    }
}

// Final GEMM epilogue: bias add + store straight to gmem
__device__ __forceinline__ void store_out(float* __restrict__ out, float acc[2][8][4],
                                          const float* __restrict__ bias, size_t obase,
                                          int nvalid, int warp, int lane) {
    const int mblk = (warp >> 1) << 5;
    const int nblk = (warp & 1) << 6;
    const int grp  = lane >> 2;
    const int tig  = lane & 3;
#pragma unroll
    for (int ni = 0; ni < 8; ni++) {
        const int c = nblk + (ni << 3) + (tig << 1);
        const float b0 = __ldg(bias + c);
        const float b1 = __ldg(bias + c + 1);
#pragma unroll
        for (int mi = 0; mi < 2; mi++) {
            const int r = mblk + (mi << 4) + grp;
            if (r < nvalid)
                *(float2*)(out + obase + (size_t)r * 128 + c) =
                    make_float2(acc[mi][ni][0] + b0, acc[mi][ni][1] + b1);
            if (r + 8 < nvalid)
                *(float2*)(out + obase + (size_t)(r + 8) * 128 + c) =
                    make_float2(acc[mi][ni][2] + b0, acc[mi][ni][3] + b1);
        }
    }
}

extern __shared__ char smem_raw[];

__global__ void __launch_bounds__(NT, 1)
urmlp_kernel(const float* __restrict__ x,
             const float* __restrict__ W1,    const float* __restrict__ b1,
             const float* __restrict__ eln1w, const float* __restrict__ eln1b,
             const float* __restrict__ ef2w,  const float* __restrict__ ef2b,
             const float* __restrict__ eln2w, const float* __restrict__ eln2b,
             const float* __restrict__ ef3w,  const float* __restrict__ ef3b,
             const float* __restrict__ ln1w,  const float* __restrict__ ln1b,
             const float* __restrict__ f2w,   const float* __restrict__ f2b,
             const float* __restrict__ ln2w,  const float* __restrict__ ln2b,
             const float* __restrict__ f3w,   const float* __restrict__ f3b,
             float* __restrict__ out)
{
    SmemT* s = (SmemT*)smem_raw;
    const int tid  = threadIdx.x;
    const int warp = tid >> 5;
    const int lane = tid & 31;

    // branch fastest-varying: 9 consecutive CTAs share one x tile (L2 reuse)
    const int bid  = blockIdx.x;
    const int tile = bid / 9;
    const int br   = bid - tile * 9;
    const int base = tile * TE;
    const int nvalid = min(TE, E_TOT - base);

    const float *pln1w, *pln1b, *pf2w, *pf2b, *pln2w, *pln2b, *pf3w, *pf3b;
    if (br == 0) {
        pln1w = eln1w; pln1b = eln1b; pf2w = ef2w; pf2b = ef2b;
        pln2w = eln2w; pln2b = eln2b; pf3w = ef3w; pf3b = ef3b;
    } else {
        const int l = br - 1;
        pln1w = ln1w + l * 128;       pln1b = ln1b + l * 128;
        pf2w  = f2w  + (size_t)l * 128 * 128; pf2b = f2b + l * 128;
        pln2w = ln2w + l * 128;       pln2b = ln2b + l * 128;
        pf3w  = f3w  + (size_t)l * 128 * 128; pf3b = f3b + l * 128;
    }

    // Load x tile, split into bf16 hi/lo; out-of-range rows -> 0 (never stored)
    for (int i = tid; i < (TE * 128) / 4; i += NT) {
        int r = i >> 5;
        int c = (i & 31) << 2;
        float4 v = (r < nvalid) ? __ldg((const float4*)(x + (size_t)(base + r) * 128 + c))
                                : make_float4(0.f, 0.f, 0.f, 0.f);
        split2(v.x, s->a_hi[r * SA + c + 0], s->a_lo[r * SA + c + 0]);
        split2(v.y, s->a_hi[r * SA + c + 1], s->a_lo[r * SA + c + 1]);
        split2(v.z, s->a_hi[r * SA + c + 2], s->a_lo[r * SA + c + 2]);
        split2(v.w, s->a_hi[r * SA + c + 3], s->a_lo[r * SA + c + 3]);
    }
    load_w_tile(s, W1 + (size_t)br * 128 * 128, tid);
    __syncthreads();

    float acc[2][8][4];

    // ---- stage 1: h = x @ W1_b^T + b1_b, LN1, SiLU ----
    gemm128(s, acc, warp, lane);
    __syncthreads();                       // all warps done reading a/w
    store_hs(s, acc, b1 + br * 128, warp, lane);
    load_w_tile(s, pf2w, tid);             // safe: gemm1 reads finished
    __syncthreads();
    ln_silu(s, pln1w, pln1b, warp, lane);  // hs -> a_hi/a_lo
    __syncthreads();

    // ---- stage 2: h = h @ fc2^T + b2, LN2, SiLU ----
    gemm128(s, acc, warp, lane);
    __syncthreads();
    store_hs(s, acc, pf2b, warp, lane);
    load_w_tile(s, pf3w, tid);
    __syncthreads();
    ln_silu(s, pln2w, pln2b, warp, lane);
    __syncthreads();

    // ---- stage 3: out = h @ fc3^T + b3 ----
    gemm128(s, acc, warp, lane);
    const size_t obase = ((size_t)br * E_TOT + base) * 128;
    store_out(out, acc, pf3b, obase, nvalid, warp, lane);
}

extern "C" void kernel_launch(void* const* d_in, const int* in_sizes, int n_in,
                              void* d_out, int out_size) {
    const float* x     = (const float*)d_in[0];
    const float* W1    = (const float*)d_in[1];
    const float* b1    = (const float*)d_in[2];
    const float* eln1w = (const float*)d_in[3];
    const float* eln1b = (const float*)d_in[4];
    const float* ef2w  = (const float*)d_in[5];
    const float* ef2b  = (const float*)d_in[6];
    const float* eln2w = (const float*)d_in[7];
    const float* eln2b = (const float*)d_in[8];
    const float* ef3w  = (const float*)d_in[9];
    const float* ef3b  = (const float*)d_in[10];
    const float* ln1w  = (const float*)d_in[11];
    const float* ln1b  = (const float*)d_in[12];
    const float* f2w   = (const float*)d_in[13];
    const float* f2b   = (const float*)d_in[14];
    const float* ln2w  = (const float*)d_in[15];
    const float* ln2b  = (const float*)d_in[16];
    const float* f3w   = (const float*)d_in[17];
    const float* f3b   = (const float*)d_in[18];
    float* out = (float*)d_out;

    cudaFuncSetAttribute(urmlp_kernel, cudaFuncAttributeMaxDynamicSharedMemorySize,
                         (int)sizeof(SmemT));

    const int tiles = (E_TOT + TE - 1) / TE;   // 1172
    urmlp_kernel<<<tiles * 9, NT, sizeof(SmemT)>>>(
        x, W1, b1, eln1w, eln1b, ef2w, ef2b, eln2w, eln2b, ef3w, ef3b,
        ln1w, ln1b, f2w, f2b, ln2w, ln2b, f3w, f3b, out);
}

// round 4
// speedup vs baseline: 2.4678x; 2.4678x over previous
#include <cuda_runtime.h>
#include <cuda_bf16.h>
#include <cstdint>
#include <cstddef>

#define E_TOT 150000
#define TE    64          // rows per CTA tile
#define NT    256         // 8 warps
#define SA    136         // bf16 smem/gmem padded row stride (elements)

// ---- smem layout (bytes) ----
#define OFF_VEC  0                       // 7 x 128 f32 = 3584
#define OFF_PART 3584                    // 2 x 64 float2 = 1024
#define OFF_A_HI 4608                    // 64*SA*2  = 17408
#define OFF_A_LO (OFF_A_HI + 17408)
#define OFF_W    (OFF_A_LO + 17408)      // hi+lo contiguous: 2*128*SA*2 = 69632
#define W_LO_B   34816
#define SMEM_SZ  (OFF_W + 69632)         // 109056 -> 2 CTAs/SM

// pre-split weights: 27 matrices, padded layout identical to smem (raw memcpy-able)
__device__ __align__(16) __nv_bfloat16 g_wsplit[27][2][128 * SA];
// pre-split x: linear [row][col]
__device__ __align__(16) __nv_bfloat16 g_xhi[(size_t)E_TOT * 128];
__device__ __align__(16) __nv_bfloat16 g_xlo[(size_t)E_TOT * 128];

// ---------------------------------------------------------------------------
__device__ __forceinline__ void split2(float v, __nv_bfloat16& hi, __nv_bfloat16& lo) {
    __nv_bfloat16 h = __float2bfloat16(v);
    hi = h;
    lo = __float2bfloat16(v - __bfloat162float(h));
}
__device__ __forceinline__ uint32_t pk(float a, float b) {
    __nv_bfloat162 t = __floats2bfloat162_rn(a, b);
    return *(uint32_t*)&t;
}
__device__ __forceinline__ void cpa16(void* saddr, const void* g) {
    uint32_t sa;
    asm("{ .reg .u64 t; cvta.to.shared.u64 t, %1; cvt.u32.u64 %0, t; }" : "=r"(sa) : "l"(saddr));
    asm volatile("cp.async.cg.shared.global [%0], [%1], 16;" :: "r"(sa), "l"(g));
}
__device__ __forceinline__ void cpa_commit() { asm volatile("cp.async.commit_group;" ::: "memory"); }
__device__ __forceinline__ void mma16816(float d[4], const uint32_t a[4],
                                         uint32_t b0, uint32_t b1) {
    asm volatile(
        "mma.sync.aligned.m16n8k16.row.col.f32.bf16.bf16.f32 "
        "{%0,%1,%2,%3}, {%4,%5,%6,%7}, {%8,%9}, {%0,%1,%2,%3};\n"
        : "+f"(d[0]), "+f"(d[1]), "+f"(d[2]), "+f"(d[3])
        : "r"(a[0]), "r"(a[1]), "r"(a[2]), "r"(a[3]), "r"(b0), "r"(b1));
}
__device__ __forceinline__ float tanhf_fast(float x) {
    float r; asm("tanh.approx.f32 %0, %1;" : "=f"(r) : "f"(x)); return r;
}
__device__ __forceinline__ float silu(float y) {
    return y * fmaf(0.5f, tanhf_fast(0.5f * y), 0.5f);
}

// ---------------------------------------------------------------------------
// prep kernels (split fp32 -> bf16 hi/lo once)
// ---------------------------------------------------------------------------
__global__ void prep_w(const float* __restrict__ W1,
                       const float* __restrict__ ef2w, const float* __restrict__ f2w,
                       const float* __restrict__ ef3w, const float* __restrict__ f3w) {
    int m = blockIdx.x;
    const float* src;
    if (m < 9)       src = W1 + (size_t)m * 16384;
    else if (m < 18) { int b = m - 9;  src = b ? f2w + (size_t)(b - 1) * 16384 : ef2w; }
    else             { int b = m - 18; src = b ? f3w + (size_t)(b - 1) * 16384 : ef3w; }
    __nv_bfloat16* hi = g_wsplit[m][0];
    __nv_bfloat16* lo = g_wsplit[m][1];
    for (int i = threadIdx.x; i < 16384; i += NT) {
        int r = i >> 7, c = i & 127;
        float v = __ldg(src + i);
        split2(v, hi[r * SA + c], lo[r * SA + c]);
    }
}

__global__ void prep_x(const float* __restrict__ x) {
    size_t i = (size_t)blockIdx.x * NT + threadIdx.x;   // one float4 per thread
    if (i >= (size_t)E_TOT * 32) return;
    float4 v = __ldg((const float4*)x + i);
    __nv_bfloat16 h0, l0, h1, l1, h2, l2, h3, l3;
    split2(v.x, h0, l0); split2(v.y, h1, l1);
    split2(v.z, h2, l2); split2(v.w, h3, l3);
    uint2 uh, ul;
    uh.x = pk(__bfloat162float(h0), __bfloat162float(h1));
    uh.y = pk(__bfloat162float(h2), __bfloat162float(h3));
    ul.x = pk(__bfloat162float(l0), __bfloat162float(l1));
    ul.y = pk(__bfloat162float(l2), __bfloat162float(l3));
    *(uint2*)(g_xhi + i * 4) = uh;
    *(uint2*)(g_xlo + i * 4) = ul;
}

// ---------------------------------------------------------------------------
// 64x128x128 GEMM from smem (split-bf16 3-product). Warp w: m-block (w>>1)*16,
// n-block (w&1)*64; 1x8 m16n8 tiles. acc[ni][4].
// ---------------------------------------------------------------------------
__device__ __forceinline__ void gemm64(char* sm, float acc[8][4], int warp, int lane) {
#pragma unroll
    for (int ni = 0; ni < 8; ni++)
#pragma unroll
        for (int j = 0; j < 4; j++) acc[ni][j] = 0.f;

    const int mblk = (warp >> 1) << 4;
    const int nblk = (warp & 1) << 6;
    const int grp  = lane >> 2;
    const int tig  = lane & 3;

#pragma unroll 1
    for (int ks = 0; ks < 8; ks++) {
        const int k0 = ks << 4;
        const int ra  = ((mblk + grp) * SA + k0 + (tig << 1)) * 2;   // bytes
        const int ra8 = ra + 8 * SA * 2;
        uint32_t ah[4], al[4];
        ah[0] = *(const uint32_t*)(sm + OFF_A_HI + ra);
        ah[1] = *(const uint32_t*)(sm + OFF_A_HI + ra8);
        ah[2] = *(const uint32_t*)(sm + OFF_A_HI + ra + 16);
        ah[3] = *(const uint32_t*)(sm + OFF_A_HI + ra8 + 16);
        al[0] = *(const uint32_t*)(sm + OFF_A_LO + ra);
        al[1] = *(const uint32_t*)(sm + OFF_A_LO + ra8);
        al[2] = *(const uint32_t*)(sm + OFF_A_LO + ra + 16);
        al[3] = *(const uint32_t*)(sm + OFF_A_LO + ra8 + 16);
#pragma unroll
        for (int ni = 0; ni < 8; ni++) {
            const int rb = ((nblk + (ni << 3) + grp) * SA + k0 + (tig << 1)) * 2;
            uint32_t bh0 = *(const uint32_t*)(sm + OFF_W + rb);
            uint32_t bh1 = *(const uint32_t*)(sm + OFF_W + rb + 16);
            uint32_t bl0 = *(const uint32_t*)(sm + OFF_W + W_LO_B + rb);
            uint32_t bl1 = *(const uint32_t*)(sm + OFF_W + W_LO_B + rb + 16);
            mma16816(acc[ni], ah, bh0, bh1);
            mma16816(acc[ni], ah, bl0, bl1);
            mma16816(acc[ni], al, bh0, bh1);
        }
    }
}

// ---------------------------------------------------------------------------
// register-resident LN+SiLU epilogue: bias add, row stats via quad-shfl +
// cross-warp float2 exchange, normalize, split-bf16 -> a_hi/a_lo
// ---------------------------------------------------------------------------
__device__ __forceinline__ void epilogue_ln(char* sm, float acc[8][4], int vecb,
                                            int warp, int lane) {
    const int grp   = lane >> 2;
    const int tig   = lane & 3;
    const int nhalf = warp & 1;
    const int nblk  = nhalf << 6;
    const int r0    = ((warp >> 1) << 4) + grp;

    const float* vec  = (const float*)(sm + OFF_VEC);
    const float* bias = vec + vecb * 128;
    const float* lw   = bias + 128;
    const float* lb   = bias + 256;

    float s0 = 0.f, q0 = 0.f, s1 = 0.f, q1 = 0.f;
#pragma unroll
    for (int ni = 0; ni < 8; ni++) {
        const int c = nblk + (ni << 3) + (tig << 1);
        const float b0 = bias[c], b1 = bias[c + 1];
        acc[ni][0] += b0; acc[ni][1] += b1;
        acc[ni][2] += b0; acc[ni][3] += b1;
        s0 += acc[ni][0] + acc[ni][1];
        q0 = fmaf(acc[ni][0], acc[ni][0], fmaf(acc[ni][1], acc[ni][1], q0));
        s1 += acc[ni][2] + acc[ni][3];
        q1 = fmaf(acc[ni][2], acc[ni][2], fmaf(acc[ni][3], acc[ni][3], q1));
    }
#pragma unroll
    for (int off = 1; off <= 2; off <<= 1) {
        s0 += __shfl_xor_sync(0xFFFFFFFFu, s0, off);
        q0 += __shfl_xor_sync(0xFFFFFFFFu, q0, off);
        s1 += __shfl_xor_sync(0xFFFFFFFFu, s1, off);
        q1 += __shfl_xor_sync(0xFFFFFFFFu, q1, off);
    }
    float2* part = (float2*)(sm + OFF_PART);
    if (tig == 0) {
        part[nhalf * 64 + r0]     = make_float2(s0, q0);
        part[nhalf * 64 + r0 + 8] = make_float2(s1, q1);
    }
    __syncthreads();
    float2 o0 = part[(1 - nhalf) * 64 + r0];
    float2 o1 = part[(1 - nhalf) * 64 + r0 + 8];
    s0 += o0.x; q0 += o0.y; s1 += o1.x; q1 += o1.y;
    const float m0 = s0 * (1.0f / 128.0f);
    const float m1 = s1 * (1.0f / 128.0f);
    const float i0 = rsqrtf(fmaf(-m0, m0, q0 * (1.0f / 128.0f)) + 1e-5f);
    const float i1 = rsqrtf(fmaf(-m1, m1, q1 * (1.0f / 128.0f)) + 1e-5f);

#pragma unroll
    for (int ni = 0; ni < 8; ni++) {
        const int c  = nblk + (ni << 3) + (tig << 1);
        const float w0 = lw[c], w1 = lw[c + 1], c0 = lb[c], c1 = lb[c + 1];
        float y00 = silu((acc[ni][0] - m0) * i0 * w0 + c0);
        float y01 = silu((acc[ni][1] - m0) * i0 * w1 + c1);
        float y10 = silu((acc[ni][2] - m1) * i1 * w0 + c0);
        float y11 = silu((acc[ni][3] - m1) * i1 * w1 + c1);
        __nv_bfloat16 h, l, h2, l2;
        const int o0b = (r0 * SA + c) * 2;
        const int o1b = ((r0 + 8) * SA + c) * 2;
        split2(y00, h, l); split2(y01, h2, l2);
        *(uint32_t*)(sm + OFF_A_HI + o0b) = pk(__bfloat162float(h), __bfloat162float(h2));
        *(uint32_t*)(sm + OFF_A_LO + o0b) = pk(__bfloat162float(l), __bfloat162float(l2));
        split2(y10, h, l); split2(y11, h2, l2);
        *(uint32_t*)(sm + OFF_A_HI + o1b) = pk(__bfloat162float(h), __bfloat162float(h2));
        *(uint32_t*)(sm + OFF_A_LO + o1b) = pk(__bfloat162float(l), __bfloat162float(l2));
    }
}

__device__ __forceinline__ void cp_weights(char* sm, int m, int tid) {
    const char* g = (const char*)g_wsplit[m];          // hi+lo contiguous 69632B
    for (int i = tid; i < 69632 / 16; i += NT)
        cpa16(sm + OFF_W + i * 16, g + (size_t)i * 16);
    cpa_commit();
}

// ---------------------------------------------------------------------------
extern __shared__ char smraw[];

__global__ void __launch_bounds__(NT, 2)
urmlp_kernel(const float* __restrict__ b1c,
             const float* __restrict__ eln1w, const float* __restrict__ eln1b,
             const float* __restrict__ ef2b,
             const float* __restrict__ eln2w, const float* __restrict__ eln2b,
             const float* __restrict__ ef3b,
             const float* __restrict__ ln1w,  const float* __restrict__ ln1b,
             const float* __restrict__ f2b,
             const float* __restrict__ ln2w,  const float* __restrict__ ln2b,
             const float* __restrict__ f3b,
             float* __restrict__ out)
{
    char* sm = smraw;
    const int tid  = threadIdx.x;
    const int warp = tid >> 5;
    const int lane = tid & 31;
    const int bid  = blockIdx.x;
    const int tile = bid / 9;
    const int br   = bid - tile * 9;
    const int base = tile * TE;
    const int nvalid = min(TE, E_TOT - base);

    // stage weights W1 (cp group)
    cp_weights(sm, br, tid);

    // stage x tile hi/lo (cp group); zero-fill invalid rows
    {
        for (int i = tid; i < TE * 16; i += NT) {       // 16 x 16B chunks per row
            const int row = i >> 4, ch = i & 15;
            char* dh = sm + OFF_A_HI + row * SA * 2 + ch * 16;
            char* dl = sm + OFF_A_LO + row * SA * 2 + ch * 16;
            if (row < nvalid) {
                const size_t go = (size_t)(base + row) * 128 + ch * 8;
                cpa16(dh, g_xhi + go);
                cpa16(dl, g_xlo + go);
            } else {
                *(uint4*)dh = make_uint4(0, 0, 0, 0);
                *(uint4*)dl = make_uint4(0, 0, 0, 0);
            }
        }
        cpa_commit();
    }

    // per-branch vectors: [b1, lw1, lb1, b2, lw2, lb2, b3]
    if (tid < 128) {
        float* vec = (float*)(sm + OFF_VEC);
        const float* s0 = b1c + br * 128;
        const float* s1 = br ? ln1w + (br - 1) * 128 : eln1w;
        const float* s2 = br ? ln1b + (br - 1) * 128 : eln1b;
        const float* s3 = br ? f2b  + (br - 1) * 128 : ef2b;
        const float* s4 = br ? ln2w + (br - 1) * 128 : eln2w;
        const float* s5 = br ? ln2b + (br - 1) * 128 : eln2b;
        const float* s6 = br ? f3b  + (br - 1) * 128 : ef3b;
        vec[0 * 128 + tid] = __ldg(s0 + tid);
        vec[1 * 128 + tid] = __ldg(s1 + tid);
        vec[2 * 128 + tid] = __ldg(s2 + tid);
        vec[3 * 128 + tid] = __ldg(s3 + tid);
        vec[4 * 128 + tid] = __ldg(s4 + tid);
        vec[5 * 128 + tid] = __ldg(s5 + tid);
        vec[6 * 128 + tid] = __ldg(s6 + tid);
    }

    asm volatile("cp.async.wait_group 0;" ::: "memory");
    __syncthreads();

    float acc[8][4];

    // ---- stage 1 ----
    gemm64(sm, acc, warp, lane);
    __syncthreads();                    // all reads of a/w done
    cp_weights(sm, 9 + br, tid);        // W2, overlaps epilogue
    epilogue_ln(sm, acc, 0, warp, lane);
    asm volatile("cp.async.wait_group 0;" ::: "memory");
    __syncthreads();

    // ---- stage 2 ----
    gemm64(sm, acc, warp, lane);
    __syncthreads();
    cp_weights(sm, 18 + br, tid);       // W3
    epilogue_ln(sm, acc, 3, warp, lane);
    asm volatile("cp.async.wait_group 0;" ::: "memory");
    __syncthreads();

    // ---- stage 3: out = h @ fc3^T + b3 ----
    gemm64(sm, acc, warp, lane);
    {
        const int grp  = lane >> 2;
        const int tig  = lane & 3;
        const int nblk = (warp & 1) << 6;
        const int r0   = ((warp >> 1) << 4) + grp;
        const float* bias = (const float*)(sm + OFF_VEC) + 6 * 128;
        float* o0 = out + ((size_t)br * E_TOT + base + r0) * 128;
        float* o1 = o0 + (size_t)8 * 128;
#pragma unroll
        for (int ni = 0; ni < 8; ni++) {
            const int c = nblk + (ni << 3) + (tig << 1);
            const float b0 = bias[c], b1 = bias[c + 1];
            if (r0 < nvalid)
                *(float2*)(o0 + c) = make_float2(acc[ni][0] + b0, acc[ni][1] + b1);
            if (r0 + 8 < nvalid)
                *(float2*)(o1 + c) = make_float2(acc[ni][2] + b0, acc[ni][3] + b1);
        }
    }
}

extern "C" void kernel_launch(void* const* d_in, const int* in_sizes, int n_in,
                              void* d_out, int out_size) {
    const float* x     = (const float*)d_in[0];
    const float* W1    = (const float*)d_in[1];
    const float* b1    = (const float*)d_in[2];
    const float* eln1w = (const float*)d_in[3];
    const float* eln1b = (const float*)d_in[4];
    const float* ef2w  = (const float*)d_in[5];
    const float* ef2b  = (const float*)d_in[6];
    const float* eln2w = (const float*)d_in[7];
    const float* eln2b = (const float*)d_in[8];
    const float* ef3w  = (const float*)d_in[9];
    const float* ef3b  = (const float*)d_in[10];
    const float* ln1w  = (const float*)d_in[11];
    const float* ln1b  = (const float*)d_in[12];
    const float* f2w   = (const float*)d_in[13];
    const float* f2b   = (const float*)d_in[14];
    const float* ln2w  = (const float*)d_in[15];
    const float* ln2b  = (const float*)d_in[16];
    const float* f3w   = (const float*)d_in[17];
    const float* f3b   = (const float*)d_in[18];
    float* out = (float*)d_out;

    cudaFuncSetAttribute(urmlp_kernel, cudaFuncAttributeMaxDynamicSharedMemorySize, SMEM_SZ);

    prep_w<<<27, NT>>>(W1, ef2w, f2w, ef3w, f3w);
    prep_x<<<(E_TOT * 32 + NT - 1) / NT, NT>>>(x);

    const int tiles = (E_TOT + TE - 1) / TE;   // 2344
    urmlp_kernel<<<tiles * 9, NT, SMEM_SZ>>>(
        b1, eln1w, eln1b, ef2b, eln2w, eln2b, ef3b,
        ln1w, ln1b, f2b, ln2w, ln2b, f3b, out);
}